// round 11
// baseline (speedup 1.0000x reference)
#include <cuda_runtime.h>
#include <cstdint>
#include <math.h>

#define SEQ 256
#define NB 64
#define HID 300
#define G4 1200
#define NTAG 12

// recurrence: 2 dirs x 8 batch-groups x 8 unit-slices = 128 CTAs
#define RBG 8           // batch groups
#define RUS 8           // unit slices
#define RBS 8           // batch per group
#define RUPC 38         // units per slice (last slice has 34)
#define R_P 76          // row pairs (152 gate rows / 2)
#define R_KS 10         // k splits (uniform 30 k each)
#define R_KCH 30
#define R_ACT 760       // active GEMV threads = 10 * 76
#define R_THREADS 768

// input projection: persistent weights; 7 seq-splits x 20 m x 2 dirs = 280 CTAs (one wave)
#define IP_MB 20
#define IP_ROWS 60
#define IP_THREADS 320
#define IP_JS 7
#define IP_SC 37
#define IP_KC 30
#define IP_NKC 10
#define IP_CHF (IP_KC * NB)
#define IP_CH4 (IP_CHF / 4)

typedef unsigned long long ull;

__device__ __forceinline__ ull pack2(float lo, float hi) {
    ull r; asm("mov.b64 %0, {%1, %2};" : "=l"(r) : "f"(lo), "f"(hi)); return r;
}
__device__ __forceinline__ void unpack2(ull v, float& lo, float& hi) {
    asm("mov.b64 {%0, %1}, %2;" : "=f"(lo), "=f"(hi) : "l"(v));
}
__device__ __forceinline__ ull fma2(ull a, ull b, ull c) {
    ull d; asm("fma.rn.f32x2 %0, %1, %2, %3;" : "=l"(d) : "l"(a), "l"(b), "l"(c)); return d;
}
__device__ __forceinline__ ull add2(ull a, ull b) {
    ull d; asm("add.rn.f32x2 %0, %1, %2;" : "=l"(d) : "l"(a), "l"(b)); return d;
}
__device__ __forceinline__ float ftanh(float x) {
    float y; asm("tanh.approx.f32 %0, %1;" : "=f"(y) : "f"(x)); return y;
}
__device__ __forceinline__ float fsigm(float x) {
    return 0.5f * ftanh(0.5f * x) + 0.5f;
}
__device__ __forceinline__ uint32_t smem_u32_of(const void* p) {
    uint32_t a;
    asm("{ .reg .u64 t0; cvta.to.shared.u64 t0, %1; cvt.u32.u64 %0, t0; }" : "=r"(a) : "l"(p));
    return a;
}
__device__ __forceinline__ void cpasync16(uint32_t saddr, const void* g) {
    asm volatile("cp.async.cg.shared.global [%0], [%1], 16;" :: "r"(saddr), "l"(g));
}

// ---------------- scratch (device globals; no allocations) ----------------
__device__ float g_XT[SEQ * HID * NB];
__device__ float g_G[2][SEQ][G4 * NB];
__device__ float g_hall[2][SEQ][RBG * HID * RBS];
__device__ float g_emit[SEQ][NB][NTAG];
__device__ int   g_cnt2[16][32];

extern __shared__ float sm[];

// ---------------- reset barrier counters ----------------
__global__ void k_reset() {
    if (threadIdx.x < 16) g_cnt2[threadIdx.x][0] = 0;
}

// ---------------- embedding gather + transpose ----------------
__global__ void k_gather(const int* __restrict__ sent, const float* __restrict__ emb) {
    int s = blockIdx.x;
    __shared__ float sx[64][33];
    __shared__ int rows[64];
    int t = threadIdx.x;  // 256
    if (t < 64) rows[t] = sent[t * SEQ + s];
    __syncthreads();
    for (int kc = 0; kc < 10; kc++) {
        int kbase = kc * 32;
        int width = HID - kbase; if (width > 32) width = 32;
        int kk = t & 31, bg = t >> 5;
        if (kk < width) {
            for (int b = bg; b < 64; b += 8)
                sx[b][kk] = emb[rows[b] * HID + kbase + kk];
        }
        __syncthreads();
        int b = t & 63, kg = t >> 6;
        for (int k2 = kg; k2 < width; k2 += 4)
            g_XT[(s * HID + kbase + k2) * NB + b] = sx[b][k2];
        __syncthreads();
    }
}

// ---------------- input projection: persistent weights, s-blocked (2 s per pass) ----------------
__global__ void __launch_bounds__(IP_THREADS, 2) k_inproj(
    const float* __restrict__ Wf, const float* __restrict__ bf,
    const float* __restrict__ Wb, const float* __restrict__ bb)
{
    int j = blockIdx.x, m = blockIdx.y, d = blockIdx.z;
    const float* W    = d ? Wb : Wf;
    const float* bias = d ? bb : bf;
    float* ws  = sm;
    float* xa0 = sm + HID * IP_ROWS;
    float* xb0 = xa0 + IP_CHF;
    float* xa1 = xb0 + IP_CHF;
    float* xb1 = xa1 + IP_CHF;
    int t = threadIdx.x;
    int u0 = m * 15;

    int s0 = j * IP_SC;
    int ns = SEQ - s0; if (ns > IP_SC) ns = IP_SC;
    int npairs = (ns + 1) >> 1;
    int slast = s0 + ns - 1;

    uint32_t xa0a = smem_u32_of(xa0), xb0a = smem_u32_of(xb0);
    uint32_t xa1a = smem_u32_of(xa1), xb1a = smem_u32_of(xb1);

    for (int idx = t; idx < HID * IP_ROWS; idx += IP_THREADS) {
        int k = idx / IP_ROWS, r = idx - k * IP_ROWS;
        int ul = r >> 2, gate = r & 3;
        ws[idx] = W[(gate * HID + u0 + ul) * HID + k];
    }

    int b = t & 63, rg = t >> 6;

    float bv[12];
    int rowv[12];
#pragma unroll
    for (int q = 0; q < 12; q++) {
        int r = rg * 12 + q;
        int row = (r & 3) * HID + u0 + (r >> 2);
        rowv[q] = row;
        bv[q] = bias[row];
    }
    __syncthreads();

    for (int pr = 0; pr < npairs; pr++) {
        int sA = s0 + 2 * pr;
        int sB = sA + 1; if (sB > slast) sB = sA;
        const float4* gA = (const float4*)(g_XT + (long long)sA * (HID * NB));
        const float4* gB = (const float4*)(g_XT + (long long)sB * (HID * NB));

#pragma unroll
        for (int q = 0; q < 3; q++) {
            int gi = t + q * IP_THREADS;
            bool isA = gi < IP_CH4;
            uint32_t dst = isA ? (xa0a + gi * 16) : (xb0a + (gi - IP_CH4) * 16);
            const float4* src = isA ? (gA + gi) : (gB + (gi - IP_CH4));
            cpasync16(dst, src);
        }
        asm volatile("cp.async.commit_group;");

        ull accA[6], accB[6];
#pragma unroll
        for (int p = 0; p < 6; p++) { accA[p] = 0ull; accB[p] = 0ull; }

        const ulonglong2* wp = ((const ulonglong2*)ws) + rg * 3;

        for (int kc = 0; kc < IP_NKC; kc++) {
            if (kc < IP_NKC - 1) {
                int nb4 = (kc + 1) * IP_CH4;
                uint32_t da = ((kc + 1) & 1) ? xa1a : xa0a;
                uint32_t db = ((kc + 1) & 1) ? xb1a : xb0a;
#pragma unroll
                for (int q = 0; q < 3; q++) {
                    int gi = t + q * IP_THREADS;
                    bool isA = gi < IP_CH4;
                    uint32_t dst = isA ? (da + gi * 16) : (db + (gi - IP_CH4) * 16);
                    const float4* src = isA ? (gA + nb4 + gi) : (gB + nb4 + (gi - IP_CH4));
                    cpasync16(dst, src);
                }
                asm volatile("cp.async.commit_group;");
                asm volatile("cp.async.wait_group 1;");
            } else {
                asm volatile("cp.async.wait_group 0;");
            }
            __syncthreads();

            const float* xpA = ((kc & 1) ? xa1 : xa0) + b;
            const float* xpB = ((kc & 1) ? xb1 : xb0) + b;
#pragma unroll 5
            for (int k = 0; k < IP_KC; k++) {
                float xa = xpA[k * NB];
                float xb = xpB[k * NB];
                ull h2a = pack2(xa, xa);
                ull h2b = pack2(xb, xb);
                ulonglong2 w0 = wp[0], w1 = wp[1], w2 = wp[2];
                accA[0] = fma2(w0.x, h2a, accA[0]);  accB[0] = fma2(w0.x, h2b, accB[0]);
                accA[1] = fma2(w0.y, h2a, accA[1]);  accB[1] = fma2(w0.y, h2b, accB[1]);
                accA[2] = fma2(w1.x, h2a, accA[2]);  accB[2] = fma2(w1.x, h2b, accB[2]);
                accA[3] = fma2(w1.y, h2a, accA[3]);  accB[3] = fma2(w1.y, h2b, accB[3]);
                accA[4] = fma2(w2.x, h2a, accA[4]);  accB[4] = fma2(w2.x, h2b, accB[4]);
                accA[5] = fma2(w2.y, h2a, accA[5]);  accB[5] = fma2(w2.y, h2b, accB[5]);
                wp += 15;
            }
            __syncthreads();
        }

        float* GdA = g_G[d][sA];
        float* GdB = g_G[d][sB];
#pragma unroll
        for (int p = 0; p < 6; p++) {
            float a0, a1, b0, b1;
            unpack2(accA[p], a0, a1);
            unpack2(accB[p], b0, b1);
            int ra = rowv[2 * p], rb = rowv[2 * p + 1];
            GdA[ra * NB + b] = a0 + bv[2 * p];
            GdA[rb * NB + b] = a1 + bv[2 * p + 1];
            GdB[ra * NB + b] = b0 + bv[2 * p];
            GdB[rb * NB + b] = b1 + bv[2 * p + 1];
        }
    }
}

// ---------------- persistent LSTM recurrence: 768 threads, 10-way k-split ----------------
// CTA = (d, g, m). smem: ws 182400B | region 48640B shared by hs (9.6KB, during stage+GEMV)
// and red (48.6KB, after GEMV — aliasing is safe: extra sync between last hs read and
// first red store; next step's stage rewrite of hs is ordered behind the poll-sync).
__global__ void __launch_bounds__(R_THREADS, 1) k_recur(
    const float* __restrict__ Whf, const float* __restrict__ Whb)
{
    int bid = blockIdx.x;
    int d = bid >> 6;
    int g = (bid >> 3) & 7;
    int m = bid & 7;
    const float* W = d ? Whb : Whf;

    float* ws = sm;                    // ws[k*152 + r], row pairs packed as ull
    float* hs = sm + HID * 152;        // hs[k*8 + bo]  (aliased region)
    ull*  red = (ull*)(sm + HID * 152);   // 8 * 760 ull  (aliased region)

    int t = threadIdx.x;
    int u0 = m * RUPC;
    int cu = HID - u0; if (cu > RUPC) cu = RUPC;

    for (int idx = t; idx < HID * 152; idx += R_THREADS) {
        int k = idx / 152, r = idx - k * 152;
        int ul = r >> 2, gate = r & 3;
        ws[idx] = (ul < cu) ? W[(gate * HID + u0 + ul) * HID + k] : 0.f;
    }
    __syncthreads();

    int ks = t / R_P;                  // 0..9 active
    int p  = t - ks * R_P;             // rowpair 0..75
    bool gemv = (t < R_ACT);
    int k0 = ks * R_KCH;
    if (!gemv) k0 = 0;
    int bp = (t < 304) ? ks : 0;       // phase2 batch-pair (= ks for t<304)
    int ul = p >> 1;
    bool doer = (t < 304) && ((p & 1) == 0) && (ul < cu);
    int boff = g * RBS + bp * 2;
    float c0 = 0.f, c1 = 0.f;
    int* cnt = &g_cnt2[d * 8 + g][0];
    const ull* wsu = (const ull*)ws;
    const ulonglong2* hsu = (const ulonglong2*)hs;

    for (int step = 0; step < SEQ; step++) {
        int pos = d ? (SEQ - 1 - step) : step;
        const float* Gp = g_G[d][pos];

        float2 Gv0, Gv1, Gv2, Gv3;
        if (doer) {
            int gb = (u0 + ul) * NB + boff;
            Gv0 = *(const float2*)(Gp + 0 * HID * NB + gb);
            Gv1 = *(const float2*)(Gp + 1 * HID * NB + gb);
            Gv2 = *(const float2*)(Gp + 2 * HID * NB + gb);
            Gv3 = *(const float2*)(Gp + 3 * HID * NB + gb);
        }

        float s0lo = 0.f, s0hi = 0.f, s1lo = 0.f, s1hi = 0.f;

        if (step > 0) {
            if (t == 0) {
                int target = RUS * step;
                int v;
                do {
                    asm volatile("ld.acquire.gpu.global.b32 %0, [%1];" : "=r"(v) : "l"(cnt) : "memory");
                    if (v < target) __nanosleep(20);
                } while (v < target);
            }
            __syncthreads();   // S1: h of prev step visible; red readers done (phase2 < S6 < here)

            {
                int prev = d ? (SEQ - step) : (step - 1);
                const float4* src = (const float4*)(g_hall[d][prev] + g * (HID * RBS));
                float4* dst = (float4*)hs;
                if (t < HID * RBS / 4) dst[t] = src[t];
            }
            __syncthreads();   // S2: hs staged

            // partial GEMV: 2 rows x 8 batches per thread over 30 k's
            ull a00 = 0, a01 = 0, a02 = 0, a03 = 0;
            ull a10 = 0, a11 = 0, a12 = 0, a13 = 0;
#pragma unroll 3
            for (int kk = 0; kk < R_KCH; kk++) {
                int k = k0 + kk;
                ull w = wsu[k * R_P + p];
                float w0, w1; unpack2(w, w0, w1);
                ull w00 = pack2(w0, w0), w11 = pack2(w1, w1);
                ulonglong2 hA = hsu[k * 2];
                ulonglong2 hB = hsu[k * 2 + 1];
                a00 = fma2(w00, hA.x, a00); a01 = fma2(w00, hA.y, a01);
                a02 = fma2(w00, hB.x, a02); a03 = fma2(w00, hB.y, a03);
                a10 = fma2(w11, hA.x, a10); a11 = fma2(w11, hA.y, a11);
                a12 = fma2(w11, hB.x, a12); a13 = fma2(w11, hB.y, a13);
            }
            __syncthreads();   // S3a: all hs reads done before red (aliased) is written

            if (gemv) {
                // red[j*760 + t], j = (rowhalf*4 + batchpair)  (8B lane stride: conflict-free)
                red[0 * R_ACT + t] = a00; red[1 * R_ACT + t] = a01;
                red[2 * R_ACT + t] = a02; red[3 * R_ACT + t] = a03;
                red[4 * R_ACT + t] = a10; red[5 * R_ACT + t] = a11;
                red[6 * R_ACT + t] = a12; red[7 * R_ACT + t] = a13;
            }
            __syncthreads();   // S3: partials visible

            // phase2: thread (p, bp) sums 10 k-splits for rows 2p,2p+1, batches 2bp,2bp+1
            if (t < 304) {
                const ull* r0 = red + bp * R_ACT + p;
                const ull* r1 = red + (4 + bp) * R_ACT + p;
                ull s0 = r0[0];
                ull s1 = r1[0];
#pragma unroll
                for (int q = 1; q < R_KS; q++) {
                    s0 = add2(s0, r0[q * R_P]);
                    s1 = add2(s1, r1[q * R_P]);
                }
                unpack2(s0, s0lo, s0hi);
                unpack2(s1, s1lo, s1hi);
            }
        }

        // exchange: even-p thread (gates i,f) pulls gates g,o from odd partner (t+1)
        float g2lo = __shfl_down_sync(0xffffffffu, s0lo, 1);
        float g2hi = __shfl_down_sync(0xffffffffu, s0hi, 1);
        float g3lo = __shfl_down_sync(0xffffffffu, s1lo, 1);
        float g3hi = __shfl_down_sync(0xffffffffu, s1hi, 1);

        if (doer) {
            float i0 = fsigm(s0lo + Gv0.x), i1 = fsigm(s0hi + Gv0.y);
            float f0 = fsigm(s1lo + Gv1.x), f1 = fsigm(s1hi + Gv1.y);
            float q0 = ftanh(g2lo + Gv2.x), q1 = ftanh(g2hi + Gv2.y);
            float o0 = fsigm(g3lo + Gv3.x), o1 = fsigm(g3hi + Gv3.y);
            c0 = f0 * c0 + i0 * q0;
            c1 = f1 * c1 + i1 * q1;
            float2 hv;
            hv.x = o0 * ftanh(c0);
            hv.y = o1 * ftanh(c1);
            *(float2*)(g_hall[d][pos] + g * (HID * RBS) + (u0 + ul) * RBS + bp * 2) = hv;
        }

        __syncthreads();   // S6: h stores done
        if (t == 0)
            asm volatile("red.release.gpu.global.add.s32 [%0], 1;" :: "l"(cnt) : "memory");
    }
}

// ---------------- emissions ----------------
__global__ void k_emit(const float* __restrict__ Wl, const float* __restrict__ bl) {
    int s = blockIdx.x, t = threadIdx.x;  // 256
    __shared__ float wl[600 * NTAG];
    __shared__ float red2[4 * NTAG * NB];
    for (int idx = t; idx < 600 * NTAG; idx += 256) {
        int k = idx / NTAG, j = idx - k * NTAG;
        wl[idx] = Wl[j * 600 + k];
    }
    __syncthreads();
    int b = t & 63, ksx = t >> 6;
    int gof = (b >> 3) * (HID * RBS) + (b & 7);
    float acc[NTAG];
#pragma unroll
    for (int j = 0; j < NTAG; j++) acc[j] = 0.f;
    const float* hf = g_hall[0][s];
    const float* hb = g_hall[1][s];
    int k0 = ksx * 150;
    for (int k = k0; k < k0 + 150; k++) {
        float v = (k < HID) ? hf[gof + k * RBS] : hb[gof + (k - HID) * RBS];
        const float4* w4 = (const float4*)(wl + k * NTAG);
#pragma unroll
        for (int q = 0; q < 3; q++) {
            float4 w = w4[q];
            acc[4 * q + 0] += w.x * v; acc[4 * q + 1] += w.y * v;
            acc[4 * q + 2] += w.z * v; acc[4 * q + 3] += w.w * v;
        }
    }
#pragma unroll
    for (int j = 0; j < NTAG; j++) red2[(ksx * NTAG + j) * NB + b] = acc[j];
    __syncthreads();
    for (int idx = t; idx < NTAG * NB; idx += 256) {
        int j = idx >> 6, b2 = idx & 63;
        float v = red2[(0 * NTAG + j) * NB + b2] + red2[(1 * NTAG + j) * NB + b2]
                + red2[(2 * NTAG + j) * NB + b2] + red2[(3 * NTAG + j) * NB + b2];
        g_emit[s][b2][j] = v + bl[j];
    }
}

// ---------------- CRF forward + gold score + loss ----------------
__global__ void k_crf(const int* __restrict__ tags, const float* __restrict__ trans,
                      float* __restrict__ out) {
    int b = blockIdx.x;
    int j = threadIdx.x;
    float Tcol[NTAG];
#pragma unroll
    for (int i = 0; i < NTAG; i++) Tcol[i] = (j < NTAG) ? trans[i * NTAG + j] : 0.f;
    float dcur = (j < NTAG) ? g_emit[0][b][j] : -1e30f;

    float ts = 0.f;
    for (int s = j; s < SEQ; s += 32) {
        int tg = tags[b * SEQ + s];
        ts += g_emit[s][b][tg];
        if (s < SEQ - 1) ts += trans[tg * NTAG + tags[b * SEQ + s + 1]];
    }
#pragma unroll
    for (int off = 16; off; off >>= 1) ts += __shfl_xor_sync(0xffffffffu, ts, off);

    for (int s = 1; s < SEQ; s++) {
        float v[NTAG];
#pragma unroll
        for (int i = 0; i < NTAG; i++)
            v[i] = __shfl_sync(0xffffffffu, dcur, i) + Tcol[i];
        float mx = v[0];
#pragma unroll
        for (int i = 1; i < NTAG; i++) mx = fmaxf(mx, v[i]);
        float sum = 0.f;
#pragma unroll
        for (int i = 0; i < NTAG; i++) sum += expf(v[i] - mx);
        float e = (j < NTAG) ? g_emit[s][b][j] : 0.f;
        dcur = e + mx + logf(sum);
    }

    float dd = (j < NTAG) ? dcur : -1e30f;
    float mm = dd;
#pragma unroll
    for (int off = 16; off; off >>= 1) mm = fmaxf(mm, __shfl_xor_sync(0xffffffffu, mm, off));
    float se = (j < NTAG) ? expf(dd - mm) : 0.f;
#pragma unroll
    for (int off = 16; off; off >>= 1) se += __shfl_xor_sync(0xffffffffu, se, off);
    if (j == 0) out[b] = mm + logf(se) - ts;
}

// ---------------- launch ----------------
extern "C" void kernel_launch(void* const* d_in, const int* in_sizes, int n_in,
                              void* d_out, int out_size) {
    const int*   sentences = (const int*)d_in[0];
    const int*   tags      = (const int*)d_in[1];
    const float* emb       = (const float*)d_in[2];
    const float* W_ih_f    = (const float*)d_in[3];
    const float* W_hh_f    = (const float*)d_in[4];
    const float* b_f       = (const float*)d_in[5];
    const float* W_ih_b    = (const float*)d_in[6];
    const float* W_hh_b    = (const float*)d_in[7];
    const float* b_b       = (const float*)d_in[8];
    const float* W_lin     = (const float*)d_in[9];
    const float* b_lin     = (const float*)d_in[10];
    const float* trans     = (const float*)d_in[11];
    float* out = (float*)d_out;

    int smem_ip = (HID * IP_ROWS + 4 * IP_CHF) * 4;                  // 102720 B
    int smem_rc = HID * 152 * 4 + R_KS * 8 /*unused pad*/ + 8 * R_ACT * 8;   // 182400 + 48640 (+80 pad)
    cudaFuncSetAttribute(k_inproj, cudaFuncAttributeMaxDynamicSharedMemorySize, smem_ip);
    cudaFuncSetAttribute(k_recur,  cudaFuncAttributeMaxDynamicSharedMemorySize, smem_rc);

    k_reset<<<1, 32>>>();
    k_gather<<<SEQ, 256>>>(sentences, emb);
    dim3 gip(IP_JS, IP_MB, 2);
    k_inproj<<<gip, IP_THREADS, smem_ip>>>(W_ih_f, b_f, W_ih_b, b_b);
    k_recur<<<2 * RBG * RUS, R_THREADS, smem_rc>>>(W_hh_f, W_hh_b);
    k_emit<<<SEQ, 256>>>(W_lin, b_lin);
    k_crf<<<NB, 32>>>(tags, trans, out);
}

// round 12
// speedup vs baseline: 1.0407x; 1.0407x over previous
#include <cuda_runtime.h>
#include <cstdint>
#include <math.h>

#define SEQ 256
#define NB 64
#define HID 300
#define G4 1200
#define NTAG 12

// recurrence: 2 dirs x 8 batch-groups x 8 unit-slices = 128 CTAs  (R10 config — best)
#define RBG 8
#define RUS 8
#define RBS 8
#define RUPC 38
#define R_P 76
#define R_KS 8
#define R_ACT 608
#define R_THREADS 640

// input projection: persistent weights; 7 seq-splits x 20 m x 2 dirs = 280 CTAs (one wave)
// s-blocked: 3 sequence positions per pass share each weight LDS
#define IP_MB 20
#define IP_ROWS 60
#define IP_THREADS 320
#define IP_JS 7
#define IP_SC 37
#define IP_KC 20
#define IP_NKC 15
#define IP_CHF (IP_KC * NB)       // 1280 floats per chunk per stream
#define IP_CH4 (IP_CHF / 4)       // 320 float4 per chunk per stream

typedef unsigned long long ull;

__device__ __forceinline__ ull pack2(float lo, float hi) {
    ull r; asm("mov.b64 %0, {%1, %2};" : "=l"(r) : "f"(lo), "f"(hi)); return r;
}
__device__ __forceinline__ void unpack2(ull v, float& lo, float& hi) {
    asm("mov.b64 {%0, %1}, %2;" : "=f"(lo), "=f"(hi) : "l"(v));
}
__device__ __forceinline__ ull fma2(ull a, ull b, ull c) {
    ull d; asm("fma.rn.f32x2 %0, %1, %2, %3;" : "=l"(d) : "l"(a), "l"(b), "l"(c)); return d;
}
__device__ __forceinline__ ull add2(ull a, ull b) {
    ull d; asm("add.rn.f32x2 %0, %1, %2;" : "=l"(d) : "l"(a), "l"(b)); return d;
}
__device__ __forceinline__ float ftanh(float x) {
    float y; asm("tanh.approx.f32 %0, %1;" : "=f"(y) : "f"(x)); return y;
}
__device__ __forceinline__ float fsigm(float x) {
    return 0.5f * ftanh(0.5f * x) + 0.5f;
}
__device__ __forceinline__ uint32_t smem_u32_of(const void* p) {
    uint32_t a;
    asm("{ .reg .u64 t0; cvta.to.shared.u64 t0, %1; cvt.u32.u64 %0, t0; }" : "=r"(a) : "l"(p));
    return a;
}
__device__ __forceinline__ void cpasync16(uint32_t saddr, const void* g) {
    asm volatile("cp.async.cg.shared.global [%0], [%1], 16;" :: "r"(saddr), "l"(g));
}

// ---------------- scratch (device globals; no allocations) ----------------
__device__ float g_XT[SEQ * HID * NB];
__device__ float g_G[2][SEQ][G4 * NB];
__device__ float g_hall[2][SEQ][RBG * HID * RBS];
__device__ float g_emit[SEQ][NB][NTAG];
__device__ int   g_cnt2[16][32];

extern __shared__ float sm[];

// ---------------- reset barrier counters ----------------
__global__ void k_reset() {
    if (threadIdx.x < 16) g_cnt2[threadIdx.x][0] = 0;
}

// ---------------- embedding gather + transpose ----------------
__global__ void k_gather(const int* __restrict__ sent, const float* __restrict__ emb) {
    int s = blockIdx.x;
    __shared__ float sx[64][33];
    __shared__ int rows[64];
    int t = threadIdx.x;  // 256
    if (t < 64) rows[t] = sent[t * SEQ + s];
    __syncthreads();
    for (int kc = 0; kc < 10; kc++) {
        int kbase = kc * 32;
        int width = HID - kbase; if (width > 32) width = 32;
        int kk = t & 31, bg = t >> 5;
        if (kk < width) {
            for (int b = bg; b < 64; b += 8)
                sx[b][kk] = emb[rows[b] * HID + kbase + kk];
        }
        __syncthreads();
        int b = t & 63, kg = t >> 6;
        for (int k2 = kg; k2 < width; k2 += 4)
            g_XT[(s * HID + kbase + k2) * NB + b] = sx[b][k2];
        __syncthreads();
    }
}

// ---------------- input projection: persistent weights, s-blocked (3 s per pass) ----------------
// CTA = (j, m, d): 60 gate rows; s in [j*37, ...) processed in triples sharing weight LDS.
// x streamed via cp.async double buffering (3 streams x 2 buffers x 20k-chunks).
__global__ void __launch_bounds__(IP_THREADS, 2) k_inproj(
    const float* __restrict__ Wf, const float* __restrict__ bf,
    const float* __restrict__ Wb, const float* __restrict__ bb)
{
    int j = blockIdx.x, m = blockIdx.y, d = blockIdx.z;
    const float* W    = d ? Wb : Wf;
    const float* bias = d ? bb : bf;
    float* ws = sm;                        // 18000 floats: ws[k*60 + r]
    float* xb = sm + HID * IP_ROWS;        // 6 x 1280 floats: [buf][stream]
    int t = threadIdx.x;
    int u0 = m * 15;

    int s0 = j * IP_SC;
    int ns = SEQ - s0; if (ns > IP_SC) ns = IP_SC;
    int ntrip = (ns + 2) / 3;
    int slast = s0 + ns - 1;

    uint32_t xb_u32 = smem_u32_of(xb);

    // stage weights once: ws[k*60 + r], r = ul*4 + gate, row = gate*300 + u0 + ul
    for (int idx = t; idx < HID * IP_ROWS; idx += IP_THREADS) {
        int k = idx / IP_ROWS, r = idx - k * IP_ROWS;
        int ul = r >> 2, gate = r & 3;
        ws[idx] = W[(gate * HID + u0 + ul) * HID + k];
    }

    int b = t & 63, rg = t >> 6;   // rg 0..4, owns rows rg*12 .. rg*12+11

    float bv[12];
    int rowv[12];
#pragma unroll
    for (int q = 0; q < 12; q++) {
        int r = rg * 12 + q;
        int row = (r & 3) * HID + u0 + (r >> 2);
        rowv[q] = row;
        bv[q] = bias[row];
    }
    __syncthreads();   // ws ready

    for (int tr = 0; tr < ntrip; tr++) {
        int sA = s0 + 3 * tr;
        int sB = sA + 1; if (sB > slast) sB = slast;
        int sC = sA + 2; if (sC > slast) sC = slast;
        const float4* gS[3];
        gS[0] = (const float4*)(g_XT + (long long)sA * (HID * NB));
        gS[1] = (const float4*)(g_XT + (long long)sB * (HID * NB));
        gS[2] = (const float4*)(g_XT + (long long)sC * (HID * NB));

        // prefetch chunk 0 into buffer 0 (thread t handles float4 index t of stream q)
#pragma unroll
        for (int q = 0; q < 3; q++) {
            uint32_t dst = xb_u32 + (q * IP_CHF + t * 4) * 4;
            cpasync16(dst, gS[q] + t);
        }
        asm volatile("cp.async.commit_group;");

        ull accA[6], accB[6], accC[6];
#pragma unroll
        for (int p = 0; p < 6; p++) { accA[p] = 0ull; accB[p] = 0ull; accC[p] = 0ull; }

        const ulonglong2* wp = ((const ulonglong2*)ws) + rg * 3;

        for (int kc = 0; kc < IP_NKC; kc++) {
            int cur = kc & 1;
            if (kc < IP_NKC - 1) {
                int nb4 = (kc + 1) * IP_CH4;
                uint32_t bufb = xb_u32 + ((kc + 1) & 1) * (3 * IP_CHF * 4);
#pragma unroll
                for (int q = 0; q < 3; q++) {
                    uint32_t dst = bufb + (q * IP_CHF + t * 4) * 4;
                    cpasync16(dst, gS[q] + nb4 + t);
                }
                asm volatile("cp.async.commit_group;");
                asm volatile("cp.async.wait_group 1;");
            } else {
                asm volatile("cp.async.wait_group 0;");
            }
            __syncthreads();   // current chunk visible

            const float* base = xb + cur * (3 * IP_CHF);
            const float* xpA = base + b;
            const float* xpB = base + IP_CHF + b;
            const float* xpC = base + 2 * IP_CHF + b;
#pragma unroll 5
            for (int k = 0; k < IP_KC; k++) {
                float xa = xpA[k * NB];
                float xv = xpB[k * NB];
                float xc = xpC[k * NB];
                ull h2a = pack2(xa, xa);
                ull h2b = pack2(xv, xv);
                ull h2c = pack2(xc, xc);
                ulonglong2 w0 = wp[0], w1 = wp[1], w2 = wp[2];
                accA[0] = fma2(w0.x, h2a, accA[0]); accB[0] = fma2(w0.x, h2b, accB[0]); accC[0] = fma2(w0.x, h2c, accC[0]);
                accA[1] = fma2(w0.y, h2a, accA[1]); accB[1] = fma2(w0.y, h2b, accB[1]); accC[1] = fma2(w0.y, h2c, accC[1]);
                accA[2] = fma2(w1.x, h2a, accA[2]); accB[2] = fma2(w1.x, h2b, accB[2]); accC[2] = fma2(w1.x, h2c, accC[2]);
                accA[3] = fma2(w1.y, h2a, accA[3]); accB[3] = fma2(w1.y, h2b, accB[3]); accC[3] = fma2(w1.y, h2c, accC[3]);
                accA[4] = fma2(w2.x, h2a, accA[4]); accB[4] = fma2(w2.x, h2b, accB[4]); accC[4] = fma2(w2.x, h2c, accC[4]);
                accA[5] = fma2(w2.y, h2a, accA[5]); accB[5] = fma2(w2.y, h2b, accB[5]); accC[5] = fma2(w2.y, h2c, accC[5]);
                wp += 15;  // 60 floats per k
            }
            __syncthreads();   // reads done before this buffer is refilled
        }

        float* GdA = g_G[d][sA];
        float* GdB = g_G[d][sB];
        float* GdC = g_G[d][sC];
#pragma unroll
        for (int p = 0; p < 6; p++) {
            float a0, a1, b0, b1, c0x, c1x;
            unpack2(accA[p], a0, a1);
            unpack2(accB[p], b0, b1);
            unpack2(accC[p], c0x, c1x);
            int ra = rowv[2 * p], rb = rowv[2 * p + 1];
            GdA[ra * NB + b] = a0 + bv[2 * p];
            GdA[rb * NB + b] = a1 + bv[2 * p + 1];
            GdB[ra * NB + b] = b0 + bv[2 * p];
            GdB[rb * NB + b] = b1 + bv[2 * p + 1];
            GdC[ra * NB + b] = c0x + bv[2 * p];
            GdC[rb * NB + b] = c1x + bv[2 * p + 1];
        }
    }
}

// ---------------- persistent LSTM recurrence: 640 threads, 8-way k-split (R10 config) ----------------
__global__ void __launch_bounds__(R_THREADS, 1) k_recur(
    const float* __restrict__ Whf, const float* __restrict__ Whb)
{
    int bid = blockIdx.x;
    int d = bid >> 6;
    int g = (bid >> 3) & 7;
    int m = bid & 7;
    const float* W = d ? Whb : Whf;

    float* ws = sm;                    // ws[k*152 + r], row pairs packed as ull
    float* hs = sm + HID * 152;        // hs[k*8 + bo]
    ull*  red = (ull*)(hs + HID * RBS);   // 8 * 608 ull

    int t = threadIdx.x;
    int u0 = m * RUPC;
    int cu = HID - u0; if (cu > RUPC) cu = RUPC;

    for (int idx = t; idx < HID * 152; idx += R_THREADS) {
        int k = idx / 152, r = idx - k * 152;
        int ul = r >> 2, gate = r & 3;
        ws[idx] = (ul < cu) ? W[(gate * HID + u0 + ul) * HID + k] : 0.f;
    }
    __syncthreads();

    int ks = t / R_P;                  // 0..7 active, 8 = spare warp
    int p  = t - ks * R_P;             // rowpair 0..75
    bool gemv = (t < R_ACT);
    int k0   = (ks < 4) ? 38 * ks : 152 + 37 * (ks - 4);
    int klen = (ks < 4) ? 38 : 37;
    if (!gemv) { k0 = 0; klen = 0; }
    int bp = (t < 304) ? ks : 0;
    int ul = p >> 1;
    bool doer = (t < 304) && ((p & 1) == 0) && (ul < cu);
    int boff = g * RBS + bp * 2;
    float c0 = 0.f, c1 = 0.f;
    int* cnt = &g_cnt2[d * 8 + g][0];
    const ull* wsu = (const ull*)ws;
    const ulonglong2* hsu = (const ulonglong2*)hs;

    for (int step = 0; step < SEQ; step++) {
        int pos = d ? (SEQ - 1 - step) : step;
        const float* Gp = g_G[d][pos];

        float2 Gv0, Gv1, Gv2, Gv3;
        if (doer) {
            int gb = (u0 + ul) * NB + boff;
            Gv0 = *(const float2*)(Gp + 0 * HID * NB + gb);
            Gv1 = *(const float2*)(Gp + 1 * HID * NB + gb);
            Gv2 = *(const float2*)(Gp + 2 * HID * NB + gb);
            Gv3 = *(const float2*)(Gp + 3 * HID * NB + gb);
        }

        float s0lo = 0.f, s0hi = 0.f, s1lo = 0.f, s1hi = 0.f;

        if (step > 0) {
            if (t == 0) {
                int target = RUS * step;
                int v;
                do {
                    asm volatile("ld.acquire.gpu.global.b32 %0, [%1];" : "=r"(v) : "l"(cnt) : "memory");
                    if (v < target) __nanosleep(20);
                } while (v < target);
            }
            __syncthreads();

            {
                int prev = d ? (SEQ - step) : (step - 1);
                const float4* src = (const float4*)(g_hall[d][prev] + g * (HID * RBS));
                float4* dst = (float4*)hs;
                if (t < HID * RBS / 4) dst[t] = src[t];
            }
            __syncthreads();

            ull a00 = 0, a01 = 0, a02 = 0, a03 = 0;
            ull a10 = 0, a11 = 0, a12 = 0, a13 = 0;
#pragma unroll 2
            for (int kk = 0; kk < klen; kk++) {
                int k = k0 + kk;
                ull w = wsu[k * R_P + p];
                float w0, w1; unpack2(w, w0, w1);
                ull w00 = pack2(w0, w0), w11 = pack2(w1, w1);
                ulonglong2 hA = hsu[k * 2];
                ulonglong2 hB = hsu[k * 2 + 1];
                a00 = fma2(w00, hA.x, a00); a01 = fma2(w00, hA.y, a01);
                a02 = fma2(w00, hB.x, a02); a03 = fma2(w00, hB.y, a03);
                a10 = fma2(w11, hA.x, a10); a11 = fma2(w11, hA.y, a11);
                a12 = fma2(w11, hB.x, a12); a13 = fma2(w11, hB.y, a13);
            }
            if (gemv) {
                red[0 * R_ACT + t] = a00; red[1 * R_ACT + t] = a01;
                red[2 * R_ACT + t] = a02; red[3 * R_ACT + t] = a03;
                red[4 * R_ACT + t] = a10; red[5 * R_ACT + t] = a11;
                red[6 * R_ACT + t] = a12; red[7 * R_ACT + t] = a13;
            }
            __syncthreads();

            if (t < 304) {
                const ull* r0 = red + bp * R_ACT + p;
                const ull* r1 = red + (4 + bp) * R_ACT + p;
                ull s0 = r0[0];
                ull s1 = r1[0];
#pragma unroll
                for (int q = 1; q < R_KS; q++) {
                    s0 = add2(s0, r0[q * R_P]);
                    s1 = add2(s1, r1[q * R_P]);
                }
                unpack2(s0, s0lo, s0hi);
                unpack2(s1, s1lo, s1hi);
            }
        }

        float g2lo = __shfl_down_sync(0xffffffffu, s0lo, 1);
        float g2hi = __shfl_down_sync(0xffffffffu, s0hi, 1);
        float g3lo = __shfl_down_sync(0xffffffffu, s1lo, 1);
        float g3hi = __shfl_down_sync(0xffffffffu, s1hi, 1);

        if (doer) {
            float i0 = fsigm(s0lo + Gv0.x), i1 = fsigm(s0hi + Gv0.y);
            float f0 = fsigm(s1lo + Gv1.x), f1 = fsigm(s1hi + Gv1.y);
            float q0 = ftanh(g2lo + Gv2.x), q1 = ftanh(g2hi + Gv2.y);
            float o0 = fsigm(g3lo + Gv3.x), o1 = fsigm(g3hi + Gv3.y);
            c0 = f0 * c0 + i0 * q0;
            c1 = f1 * c1 + i1 * q1;
            float2 hv;
            hv.x = o0 * ftanh(c0);
            hv.y = o1 * ftanh(c1);
            *(float2*)(g_hall[d][pos] + g * (HID * RBS) + (u0 + ul) * RBS + bp * 2) = hv;
        }

        __syncthreads();
        if (t == 0)
            asm volatile("red.release.gpu.global.add.s32 [%0], 1;" :: "l"(cnt) : "memory");
    }
}

// ---------------- emissions ----------------
__global__ void k_emit(const float* __restrict__ Wl, const float* __restrict__ bl) {
    int s = blockIdx.x, t = threadIdx.x;  // 256
    __shared__ float wl[600 * NTAG];
    __shared__ float red2[4 * NTAG * NB];
    for (int idx = t; idx < 600 * NTAG; idx += 256) {
        int k = idx / NTAG, j = idx - k * NTAG;
        wl[idx] = Wl[j * 600 + k];
    }
    __syncthreads();
    int b = t & 63, ksx = t >> 6;
    int gof = (b >> 3) * (HID * RBS) + (b & 7);
    float acc[NTAG];
#pragma unroll
    for (int j = 0; j < NTAG; j++) acc[j] = 0.f;
    const float* hf = g_hall[0][s];
    const float* hb = g_hall[1][s];
    int k0 = ksx * 150;
    for (int k = k0; k < k0 + 150; k++) {
        float v = (k < HID) ? hf[gof + k * RBS] : hb[gof + (k - HID) * RBS];
        const float4* w4 = (const float4*)(wl + k * NTAG);
#pragma unroll
        for (int q = 0; q < 3; q++) {
            float4 w = w4[q];
            acc[4 * q + 0] += w.x * v; acc[4 * q + 1] += w.y * v;
            acc[4 * q + 2] += w.z * v; acc[4 * q + 3] += w.w * v;
        }
    }
#pragma unroll
    for (int j = 0; j < NTAG; j++) red2[(ksx * NTAG + j) * NB + b] = acc[j];
    __syncthreads();
    for (int idx = t; idx < NTAG * NB; idx += 256) {
        int j = idx >> 6, b2 = idx & 63;
        float v = red2[(0 * NTAG + j) * NB + b2] + red2[(1 * NTAG + j) * NB + b2]
                + red2[(2 * NTAG + j) * NB + b2] + red2[(3 * NTAG + j) * NB + b2];
        g_emit[s][b2][j] = v + bl[j];
    }
}

// ---------------- CRF forward + gold score + loss ----------------
__global__ void k_crf(const int* __restrict__ tags, const float* __restrict__ trans,
                      float* __restrict__ out) {
    int b = blockIdx.x;
    int j = threadIdx.x;
    float Tcol[NTAG];
#pragma unroll
    for (int i = 0; i < NTAG; i++) Tcol[i] = (j < NTAG) ? trans[i * NTAG + j] : 0.f;
    float dcur = (j < NTAG) ? g_emit[0][b][j] : -1e30f;

    float ts = 0.f;
    for (int s = j; s < SEQ; s += 32) {
        int tg = tags[b * SEQ + s];
        ts += g_emit[s][b][tg];
        if (s < SEQ - 1) ts += trans[tg * NTAG + tags[b * SEQ + s + 1]];
    }
#pragma unroll
    for (int off = 16; off; off >>= 1) ts += __shfl_xor_sync(0xffffffffu, ts, off);

    for (int s = 1; s < SEQ; s++) {
        float v[NTAG];
#pragma unroll
        for (int i = 0; i < NTAG; i++)
            v[i] = __shfl_sync(0xffffffffu, dcur, i) + Tcol[i];
        float mx = v[0];
#pragma unroll
        for (int i = 1; i < NTAG; i++) mx = fmaxf(mx, v[i]);
        float sum = 0.f;
#pragma unroll
        for (int i = 0; i < NTAG; i++) sum += expf(v[i] - mx);
        float e = (j < NTAG) ? g_emit[s][b][j] : 0.f;
        dcur = e + mx + logf(sum);
    }

    float dd = (j < NTAG) ? dcur : -1e30f;
    float mm = dd;
#pragma unroll
    for (int off = 16; off; off >>= 1) mm = fmaxf(mm, __shfl_xor_sync(0xffffffffu, mm, off));
    float se = (j < NTAG) ? expf(dd - mm) : 0.f;
#pragma unroll
    for (int off = 16; off; off >>= 1) se += __shfl_xor_sync(0xffffffffu, se, off);
    if (j == 0) out[b] = mm + logf(se) - ts;
}

// ---------------- launch ----------------
extern "C" void kernel_launch(void* const* d_in, const int* in_sizes, int n_in,
                              void* d_out, int out_size) {
    const int*   sentences = (const int*)d_in[0];
    const int*   tags      = (const int*)d_in[1];
    const float* emb       = (const float*)d_in[2];
    const float* W_ih_f    = (const float*)d_in[3];
    const float* W_hh_f    = (const float*)d_in[4];
    const float* b_f       = (const float*)d_in[5];
    const float* W_ih_b    = (const float*)d_in[6];
    const float* W_hh_b    = (const float*)d_in[7];
    const float* b_b       = (const float*)d_in[8];
    const float* W_lin     = (const float*)d_in[9];
    const float* b_lin     = (const float*)d_in[10];
    const float* trans     = (const float*)d_in[11];
    float* out = (float*)d_out;

    int smem_ip = (HID * IP_ROWS + 6 * IP_CHF) * 4;                   // 102720 B
    int smem_rc = (HID * 152 + HID * RBS) * 4 + R_KS * R_ACT * 8;     // 230912 B
    cudaFuncSetAttribute(k_inproj, cudaFuncAttributeMaxDynamicSharedMemorySize, smem_ip);
    cudaFuncSetAttribute(k_recur,  cudaFuncAttributeMaxDynamicSharedMemorySize, smem_rc);

    k_reset<<<1, 32>>>();
    k_gather<<<SEQ, 256>>>(sentences, emb);
    dim3 gip(IP_JS, IP_MB, 2);
    k_inproj<<<gip, IP_THREADS, smem_ip>>>(W_ih_f, b_f, W_ih_b, b_b);
    k_recur<<<2 * RBG * RUS, R_THREADS, smem_rc>>>(W_hh_f, W_hh_b);
    k_emit<<<SEQ, 256>>>(W_lin, b_lin);
    k_crf<<<NB, 32>>>(tags, trans, out);
}